// round 7
// baseline (speedup 1.0000x reference)
#include <cuda_runtime.h>
#include <cuda_bf16.h>
#include <cstdint>

// Problem constants (fixed by the dataset)
#define NN 50000
#define EE 800000
#define DIN 128
#define HC 128      // H*C
#define CC 64       // per-head channels
#define HH 2
#define ED 32

typedef unsigned long long ULL;

// ---------------------------------------------------------------------------
// Scratch layout (floats). int regions aliased.
//   q   : N*128                      @ 0
//   kv  : N*256 (k row | v row)      @ 6.4M
//   p   : N*64                       @ 19.2M
//   num : N*128                      @ 22.4M
//   r   : N*64                       @ 28.8M
//   den : N*2                        @ 32.0M
// ---------------------------------------------------------------------------
#define OFF_Q    ((size_t)0)
#define OFF_KV   ((size_t)6400000)
#define OFF_P    ((size_t)19200000)
#define OFF_NUM  ((size_t)22400000)
#define OFF_R    ((size_t)28800000)
#define OFF_DEN  ((size_t)32000000)
#define OFF_CNT  ((size_t)32100000)
#define OFF_OFFS ((size_t)32160000)
#define OFF_CURS ((size_t)32220000)
#define OFF_ES   ((size_t)32280000)   // int2 per edge (e, src)
#define OFF_BSUM ((size_t)33880000)
#define BUF_TOTAL ((size_t)33880128)

__device__ float g_buf[BUF_TOTAL];

// ---------------------------------------------------------------------------
// Packed fp32x2 helpers (Blackwell FFMA2 path — only reachable via PTX)
// ---------------------------------------------------------------------------
__device__ __forceinline__ void ffma2(ULL &d, ULL a, ULL b) {
    asm volatile("fma.rn.f32x2 %0, %1, %2, %3;" : "=l"(d) : "l"(a), "l"(b), "l"(d));
}
__device__ __forceinline__ ULL packdup(float x) {
    ULL r; asm("mov.b64 %0, {%1, %2};" : "=l"(r) : "f"(x), "f"(x)); return r;
}
__device__ __forceinline__ float2 unpack2(ULL v) {
    float2 r; asm("mov.b64 {%0, %1}, %2;" : "=f"(r.x), "=f"(r.y) : "l"(v)); return r;
}

// ---------------------------------------------------------------------------
// Kernel 1: fused node GEMMs (q,k,v,skip). 128x128 tile, FFMA2.
// k and v are written interleaved into kv (stride 256) for gather locality.
// ---------------------------------------------------------------------------
#define ASTRIDE 130

__global__ __launch_bounds__(256, 2)
void gemm_qkvs(const float* __restrict__ x, int Nn,
               const float* __restrict__ Wq, const float* __restrict__ bq,
               const float* __restrict__ Wk, const float* __restrict__ bk,
               const float* __restrict__ Wv, const float* __restrict__ bv,
               const float* __restrict__ Ws, const float* __restrict__ bs,
               float* __restrict__ gq, float* __restrict__ gkv,
               float* __restrict__ gout)
{
    __shared__ __align__(16) float As[32 * ASTRIDE];
    __shared__ __align__(16) float Bs[32 * 128];

    const float* W; const float* bias; float* out; int ostride;
    int m = blockIdx.y;
    if (m == 0)      { W = Wq; bias = bq; out = gq;        ostride = 128; }
    else if (m == 1) { W = Wk; bias = bk; out = gkv;       ostride = 256; }
    else if (m == 2) { W = Wv; bias = bv; out = gkv + 128; ostride = 256; }
    else             { W = Ws; bias = bs; out = gout;      ostride = 128; }

    int rowBase = blockIdx.x * 128;
    int tid = threadIdx.x;
    int tx = tid & 15;
    int ty = tid >> 4;

    ULL acc[4][8];
    #pragma unroll
    for (int i = 0; i < 4; i++)
        #pragma unroll
        for (int j = 0; j < 8; j++) acc[i][j] = 0ull;

    #pragma unroll
    for (int kt = 0; kt < 4; kt++) {
        int k0 = kt * 32;
        #pragma unroll
        for (int it = 0; it < 4; it++) {
            int fi  = tid + it * 256;
            int row = fi >> 3;
            int c4  = fi & 7;
            int gr  = rowBase + row;
            float4 v = make_float4(0.f, 0.f, 0.f, 0.f);
            if (gr < Nn) v = *(const float4*)(x + (size_t)gr * DIN + k0 + c4 * 4);
            As[(c4 * 4 + 0) * ASTRIDE + row] = v.x;
            As[(c4 * 4 + 1) * ASTRIDE + row] = v.y;
            As[(c4 * 4 + 2) * ASTRIDE + row] = v.z;
            As[(c4 * 4 + 3) * ASTRIDE + row] = v.w;
        }
        #pragma unroll
        for (int it = 0; it < 4; it++) {
            int fi = tid + it * 256;
            int kk = fi >> 5;
            int c4 = fi & 31;
            *(float4*)(&Bs[kk * 128 + c4 * 4]) =
                *(const float4*)(W + (size_t)(k0 + kk) * HC + c4 * 4);
        }
        __syncthreads();

        #pragma unroll
        for (int k = 0; k < 32; k++) {
            const ULL* ap = (const ULL*)(&As[k * ASTRIDE + ty * 8]);
            ULL a0 = ap[0], a1 = ap[1], a2 = ap[2], a3 = ap[3];
            float4 b03 = *(const float4*)(&Bs[k * 128 + tx * 8]);
            float4 b47 = *(const float4*)(&Bs[k * 128 + tx * 8 + 4]);
            ULL bd[8];
            bd[0] = packdup(b03.x); bd[1] = packdup(b03.y);
            bd[2] = packdup(b03.z); bd[3] = packdup(b03.w);
            bd[4] = packdup(b47.x); bd[5] = packdup(b47.y);
            bd[6] = packdup(b47.z); bd[7] = packdup(b47.w);
            #pragma unroll
            for (int j = 0; j < 8; j++) {
                ffma2(acc[0][j], a0, bd[j]);
                ffma2(acc[1][j], a1, bd[j]);
                ffma2(acc[2][j], a2, bd[j]);
                ffma2(acc[3][j], a3, bd[j]);
            }
        }
        __syncthreads();
    }

    #pragma unroll
    for (int j = 0; j < 8; j++) {
        int col = tx * 8 + j;
        float bv = __ldg(bias + col);
        #pragma unroll
        for (int i2 = 0; i2 < 4; i2++) {
            float2 v = unpack2(acc[i2][j]);
            int gr = rowBase + ty * 8 + i2 * 2;
            if (gr < Nn)     out[(size_t)gr * ostride + col]       = v.x + bv;
            if (gr + 1 < Nn) out[(size_t)(gr + 1) * ostride + col] = v.y + bv;
        }
    }
}

// ---------------------------------------------------------------------------
// Kernel 2: p[n][h*32+d] = sum_{c<64} q[n][h*64+c] * We[d][h*64+c]
// ---------------------------------------------------------------------------
__global__ __launch_bounds__(256)
void p_kernel(const float* __restrict__ gq, const float* __restrict__ We,
              float* __restrict__ gp, int Nn)
{
    __shared__ float Ws[32 * 129];
    for (int i = threadIdx.x; i < ED * HC; i += blockDim.x)
        Ws[(i >> 7) * 129 + (i & 127)] = __ldg(&We[i]);
    __syncthreads();

    int warpId = (blockIdx.x * blockDim.x + threadIdx.x) >> 5;
    int lane   = threadIdx.x & 31;
    int nw     = (gridDim.x * blockDim.x) >> 5;

    for (int n = warpId; n < Nn; n += nw) {
        const float* qb = gq + (size_t)n * HC;
        const float* wrow = &Ws[lane * 129];
        float acc0 = 0.f, acc1 = 0.f;
        #pragma unroll
        for (int c4 = 0; c4 < 16; c4++) {
            float4 qa = *(const float4*)(qb + c4 * 4);
            float4 qc = *(const float4*)(qb + 64 + c4 * 4);
            acc0 += qa.x * wrow[c4 * 4]     + qa.y * wrow[c4 * 4 + 1]
                  + qa.z * wrow[c4 * 4 + 2] + qa.w * wrow[c4 * 4 + 3];
            acc1 += qc.x * wrow[64 + c4 * 4]     + qc.y * wrow[64 + c4 * 4 + 1]
                  + qc.z * wrow[64 + c4 * 4 + 2] + qc.w * wrow[64 + c4 * 4 + 3];
        }
        gp[(size_t)n * 64 + lane]      = acc0;
        gp[(size_t)n * 64 + 32 + lane] = acc1;
    }
}

// ---------------------------------------------------------------------------
// CSR build: histogram -> 3-phase parallel scan -> scatter (int2 stream)
// ---------------------------------------------------------------------------
__global__ void hist_kernel(const int* __restrict__ ei, int* __restrict__ cnt, int E)
{
    int e = blockIdx.x * blockDim.x + threadIdx.x;
    if (e < E) atomicAdd(&cnt[__ldg(&ei[E + e])], 1);
}

__global__ __launch_bounds__(1024)
void scan_block(const int* __restrict__ cnt, int* __restrict__ offs,
                int* __restrict__ bsum, int Nn)
{
    __shared__ int wsum[32];
    int tid = threadIdx.x, lane = tid & 31, wid = tid >> 5;
    int i = blockIdx.x * 1024 + tid;
    int v = (i < Nn) ? cnt[i] : 0;
    int x = v;
    #pragma unroll
    for (int o = 1; o < 32; o <<= 1) {
        int t = __shfl_up_sync(0xffffffffu, x, o);
        if (lane >= o) x += t;
    }
    if (lane == 31) wsum[wid] = x;
    __syncthreads();
    if (wid == 0) {
        int s = wsum[lane];
        #pragma unroll
        for (int o = 1; o < 32; o <<= 1) {
            int t = __shfl_up_sync(0xffffffffu, s, o);
            if (lane >= o) s += t;
        }
        wsum[lane] = s;
    }
    __syncthreads();
    int wbase = (wid == 0) ? 0 : wsum[wid - 1];
    if (i < Nn) offs[i] = wbase + x - v;
    if (tid == 1023) bsum[blockIdx.x] = wsum[31];
}

__global__ void scan_tops(int* __restrict__ bsum, int* __restrict__ offs, int Nn, int nb)
{
    if (threadIdx.x == 0) {
        int run = 0;
        for (int b = 0; b < nb; b++) { int t = bsum[b]; bsum[b] = run; run += t; }
        offs[Nn] = run;
    }
}

__global__ __launch_bounds__(1024)
void scan_add(int* __restrict__ offs, int* __restrict__ curs,
              const int* __restrict__ bsum, int Nn)
{
    int i = blockIdx.x * 1024 + threadIdx.x;
    if (i < Nn) {
        int o = offs[i] + __ldg(&bsum[blockIdx.x]);
        offs[i] = o;
        curs[i] = o;
    }
}

__global__ void scatter_kernel(const int* __restrict__ ei, int* __restrict__ curs,
                               int2* __restrict__ es, int E)
{
    int e = blockIdx.x * blockDim.x + threadIdx.x;
    if (e < E) {
        int d = __ldg(&ei[E + e]);
        int pos = atomicAdd(&curs[d], 1);
        es[pos] = make_int2(e, __ldg(&ei[e]));
    }
}

// ---------------------------------------------------------------------------
// Kernel 3: dst-stationary edge aggregation. One warp per dst node.
// Lane l owns contiguous channels [4l, 4l+4); lanes 0-15 = head 0, 16-31 = head 1.
// Streaming loads (__ldcs) for es and ea keep the k/v gather set L2-resident.
// es prefetched one iteration ahead to break the es->addr->LDG chain.
// ---------------------------------------------------------------------------
__global__ __launch_bounds__(256)
void edge_agg(const int* __restrict__ offs, const int2* __restrict__ es,
              const float* __restrict__ ea,
              const float* __restrict__ gq, const float* __restrict__ gkv,
              const float* __restrict__ gp,
              float* __restrict__ gnum, float* __restrict__ gr,
              float* __restrict__ gden, int Nn)
{
    int lane = threadIdx.x & 31;
    int n = blockIdx.x * 8 + (threadIdx.x >> 5);
    if (n >= Nn) return;

    int h = lane >> 4;          // head
    int j = lane & 15;          // lane within head

    int beg = __ldg(&offs[n]);
    int end = __ldg(&offs[n + 1]);

    float4 q4 = __ldg((const float4*)(gq + (size_t)n * HC + 4 * lane));
    float2 p2 = __ldg((const float2*)(gp + (size_t)n * 64 + h * 32 + 2 * j));

    float a0 = 0.f, a1 = 0.f, a2 = 0.f, a3 = 0.f;
    float r0 = 0.f, r1 = 0.f, dw = 0.f;

    int i = beg;
    int2 nA, nB;
    if (i + 2 <= end) { nA = __ldcs(&es[i]); nB = __ldcs(&es[i + 1]); }

    for (; i + 2 <= end; ) {
        int2 eA = nA, eB = nB;
        i += 2;
        if (i + 2 <= end) { nA = __ldcs(&es[i]); nB = __ldcs(&es[i + 1]); }

        const float* kvA = gkv + (size_t)eA.y * 256 + 4 * lane;
        const float* kvB = gkv + (size_t)eB.y * 256 + 4 * lane;
        float4 kA = __ldg((const float4*)kvA);
        float4 kB = __ldg((const float4*)kvB);
        float4 vA = __ldg((const float4*)(kvA + 128));
        float4 vB = __ldg((const float4*)(kvB + 128));
        float2 cA = __ldcs((const float2*)(ea + (size_t)eA.x * ED + 2 * j));
        float2 cB = __ldcs((const float2*)(ea + (size_t)eB.x * ED + 2 * j));

        float sA = q4.x * kA.x + q4.y * kA.y + q4.z * kA.z + q4.w * kA.w
                 + cA.x * p2.x + cA.y * p2.y;
        float sB = q4.x * kB.x + q4.y * kB.y + q4.z * kB.z + q4.w * kB.w
                 + cB.x * p2.x + cB.y * p2.y;
        #pragma unroll
        for (int o = 8; o > 0; o >>= 1) {
            sA += __shfl_xor_sync(0xffffffffu, sA, o);
            sB += __shfl_xor_sync(0xffffffffu, sB, o);
        }
        float wA = __expf(sA * 0.125f);   // 1/sqrt(64)
        float wB = __expf(sB * 0.125f);

        a0 += wA * vA.x + wB * vB.x;
        a1 += wA * vA.y + wB * vB.y;
        a2 += wA * vA.z + wB * vB.z;
        a3 += wA * vA.w + wB * vB.w;
        r0 += wA * cA.x + wB * cB.x;
        r1 += wA * cA.y + wB * cB.y;
        dw += wA + wB;
    }
    if (i < end) {
        int2 eA = __ldcs(&es[i]);
        const float* kvA = gkv + (size_t)eA.y * 256 + 4 * lane;
        float4 kA = __ldg((const float4*)kvA);
        float4 vA = __ldg((const float4*)(kvA + 128));
        float2 cA = __ldcs((const float2*)(ea + (size_t)eA.x * ED + 2 * j));
        float sA = q4.x * kA.x + q4.y * kA.y + q4.z * kA.z + q4.w * kA.w
                 + cA.x * p2.x + cA.y * p2.y;
        #pragma unroll
        for (int o = 8; o > 0; o >>= 1)
            sA += __shfl_xor_sync(0xffffffffu, sA, o);
        float wA = __expf(sA * 0.125f);
        a0 += wA * vA.x; a1 += wA * vA.y; a2 += wA * vA.z; a3 += wA * vA.w;
        r0 += wA * cA.x; r1 += wA * cA.y;
        dw += wA;
    }

    *(float4*)(gnum + (size_t)n * HC + 4 * lane) = make_float4(a0, a1, a2, a3);
    *(float2*)(gr + (size_t)n * 64 + h * 32 + 2 * j) = make_float2(r0, r1);
    if (j == 0) gden[2 * n + h] = dw;
}

// ---------------------------------------------------------------------------
// Kernel 4: finalize as FFMA2 GEMM.
//   rW = r[N,64] @ Bblk[64,128]  (Bblk = block-diag of We halves)
//   out[n][c] += (num[n][c] + rW[n][c]) / (den[n][h] + 1e-16)
// ---------------------------------------------------------------------------
__global__ __launch_bounds__(256, 2)
void finalize_gemm(const float* __restrict__ r, const float* __restrict__ num,
                   const float* __restrict__ den, const float* __restrict__ We,
                   float* __restrict__ out, int Nn)
{
    __shared__ __align__(16) float As[32 * ASTRIDE];
    __shared__ __align__(16) float Bs[32 * 128];

    int rowBase = blockIdx.x * 128;
    int tid = threadIdx.x;
    int tx = tid & 15;
    int ty = tid >> 4;

    ULL acc[4][8];
    #pragma unroll
    for (int i = 0; i < 4; i++)
        #pragma unroll
        for (int j = 0; j < 8; j++) acc[i][j] = 0ull;

    #pragma unroll
    for (int kt = 0; kt < 2; kt++) {
        int k0 = kt * 32;
        #pragma unroll
        for (int it = 0; it < 4; it++) {
            int fi  = tid + it * 256;
            int row = fi >> 3;
            int c4  = fi & 7;
            int gr  = rowBase + row;
            float4 v = make_float4(0.f, 0.f, 0.f, 0.f);
            if (gr < Nn) v = *(const float4*)(r + (size_t)gr * 64 + k0 + c4 * 4);
            As[(c4 * 4 + 0) * ASTRIDE + row] = v.x;
            As[(c4 * 4 + 1) * ASTRIDE + row] = v.y;
            As[(c4 * 4 + 2) * ASTRIDE + row] = v.z;
            As[(c4 * 4 + 3) * ASTRIDE + row] = v.w;
        }
        #pragma unroll
        for (int it = 0; it < 4; it++) {
            int fi = tid + it * 256;
            int kk = fi >> 5;
            int c  = (fi & 31) * 4;
            int d  = k0 + kk;
            float4 w = make_float4(0.f, 0.f, 0.f, 0.f);
            if (d < 32) {
                if (c < 64) w = *(const float4*)(We + (size_t)d * HC + c);
            } else {
                if (c >= 64) w = *(const float4*)(We + (size_t)(d - 32) * HC + c);
            }
            *(float4*)(&Bs[kk * 128 + c]) = w;
        }
        __syncthreads();

        #pragma unroll
        for (int k = 0; k < 32; k++) {
            const ULL* ap = (const ULL*)(&As[k * ASTRIDE + ty * 8]);
            ULL a0 = ap[0], a1 = ap[1], a2 = ap[2], a3 = ap[3];
            float4 b03 = *(const float4*)(&Bs[k * 128 + tx * 8]);
            float4 b47 = *(const float4*)(&Bs[k * 128 + tx * 8 + 4]);
            ULL bd[8];
            bd[0] = packdup(b03.x); bd[1] = packdup(b03.y);
            bd[2] = packdup(b03.z); bd[3] = packdup(b03.w);
            bd[4] = packdup(b47.x); bd[5] = packdup(b47.y);
            bd[6] = packdup(b47.z); bd[7] = packdup(b47.w);
            #pragma unroll
            for (int j = 0; j < 8; j++) {
                ffma2(acc[0][j], a0, bd[j]);
                ffma2(acc[1][j], a1, bd[j]);
                ffma2(acc[2][j], a2, bd[j]);
                ffma2(acc[3][j], a3, bd[j]);
            }
        }
        __syncthreads();
    }

    #pragma unroll
    for (int j = 0; j < 8; j++) {
        int col = tx * 8 + j;
        int h   = col >> 6;
        #pragma unroll
        for (int i2 = 0; i2 < 4; i2++) {
            float2 v = unpack2(acc[i2][j]);
            int gr = rowBase + ty * 8 + i2 * 2;
            if (gr < Nn) {
                float inv = 1.0f / (__ldg(den + 2 * gr + h) + 1e-16f);
                out[(size_t)gr * HC + col] += (num[(size_t)gr * HC + col] + v.x) * inv;
            }
            if (gr + 1 < Nn) {
                float inv = 1.0f / (__ldg(den + 2 * (gr + 1) + h) + 1e-16f);
                out[(size_t)(gr + 1) * HC + col] += (num[(size_t)(gr + 1) * HC + col] + v.y) * inv;
            }
        }
    }
}

// ---------------------------------------------------------------------------
// Launch. Order chosen so gemm_qkvs is the 4th kernel launch (ncu capture slot).
// All kernels on the default stream; dependencies are stream-serial.
// ---------------------------------------------------------------------------
extern "C" void kernel_launch(void* const* d_in, const int* in_sizes, int n_in,
                              void* d_out, int out_size)
{
    const float* x     = (const float*)d_in[0];
    const int*   ei    = (const int*)d_in[1];
    const float* ea    = (const float*)d_in[2];
    const float* Wq    = (const float*)d_in[3];
    const float* bq    = (const float*)d_in[4];
    const float* Wk    = (const float*)d_in[5];
    const float* bk    = (const float*)d_in[6];
    const float* Wv    = (const float*)d_in[7];
    const float* bv    = (const float*)d_in[8];
    const float* We    = (const float*)d_in[9];
    const float* Wsk   = (const float*)d_in[10];
    const float* bsk   = (const float*)d_in[11];
    float*       out   = (float*)d_out;

    int Nn = in_sizes[0] / DIN;
    int E  = in_sizes[1] / 2;

    float* base = nullptr;
    cudaGetSymbolAddress((void**)&base, g_buf);
    float* gq   = base + OFF_Q;
    float* gkv  = base + OFF_KV;
    float* gp   = base + OFF_P;
    float* gnum = base + OFF_NUM;
    float* gr   = base + OFF_R;
    float* gden = base + OFF_DEN;
    int*   cnt  = (int*)(base + OFF_CNT);
    int*   offs = (int*)(base + OFF_OFFS);
    int*   curs = (int*)(base + OFF_CURS);
    int2*  es   = (int2*)(base + OFF_ES);
    int*   bsum = (int*)(base + OFF_BSUM);

    int eb = (E + 255) / 256;
    int nb = (Nn + 1023) / 1024;

    // zero only the degree histogram
    cudaMemsetAsync(cnt, 0, (size_t)Nn * sizeof(int), 0);

    // K1-K3: CSR front half
    hist_kernel<<<eb, 256>>>(ei, cnt, E);
    scan_block<<<nb, 1024>>>(cnt, offs, bsum, Nn);
    scan_tops<<<1, 32>>>(bsum, offs, Nn, nb);

    // K4 (ncu capture slot): node GEMMs
    dim3 ggrid((Nn + 127) / 128, 4);
    gemm_qkvs<<<ggrid, 256>>>(x, Nn, Wq, bq, Wk, bk, Wv, bv, Wsk, bsk,
                              gq, gkv, out);

    // K5-K6: CSR back half
    scan_add<<<nb, 1024>>>(offs, curs, bsum, Nn);
    scatter_kernel<<<eb, 256>>>(ei, curs, es, E);

    // K7: p = q contracted with We (per head)
    p_kernel<<<1480, 256>>>(gq, We, gp, Nn);

    // K8: dst-stationary aggregation (no atomics)
    edge_agg<<<(Nn + 7) / 8, 256>>>(offs, es, ea, gq, gkv, gp,
                                    gnum, gr, gden, Nn);

    // K9: finalize: rW GEMM + normalize + skip
    finalize_gemm<<<(Nn + 127) / 128, 256>>>(gr, gnum, gden, We, out, Nn);
}

// round 9
// speedup vs baseline: 1.3340x; 1.3340x over previous
#include <cuda_runtime.h>
#include <cuda_bf16.h>
#include <cstdint>

// Problem constants (fixed by the dataset)
#define NN 50000
#define EE 800000
#define DIN 128
#define HC 128      // H*C
#define CC 64       // per-head channels
#define HH 2
#define ED 32

typedef unsigned long long ULL;

// ---------------------------------------------------------------------------
// Scratch layout (floats). int regions aliased.
// ---------------------------------------------------------------------------
#define OFF_Q    ((size_t)0)
#define OFF_K    ((size_t)6400000)
#define OFF_V    ((size_t)12800000)
#define OFF_P    ((size_t)19200000)
#define OFF_NUM  ((size_t)22400000)
#define OFF_R    ((size_t)28800000)
#define OFF_DEN  ((size_t)32000000)
#define OFF_CNT  ((size_t)32100000)
#define OFF_OFFS ((size_t)32160000)
#define OFF_CURS ((size_t)32220000)
#define OFF_ES   ((size_t)32280000)   // int2 per edge (e, src)
#define OFF_BSUM ((size_t)33880000)
#define BUF_TOTAL ((size_t)33880128)

__device__ float g_buf[BUF_TOTAL];

// ---------------------------------------------------------------------------
// Packed fp32x2 helpers (Blackwell FFMA2 path — only reachable via PTX)
// ---------------------------------------------------------------------------
__device__ __forceinline__ void ffma2(ULL &d, ULL a, ULL b) {
    asm volatile("fma.rn.f32x2 %0, %1, %2, %3;" : "=l"(d) : "l"(a), "l"(b), "l"(d));
}
__device__ __forceinline__ ULL packdup(float x) {
    ULL r; asm("mov.b64 %0, {%1, %2};" : "=l"(r) : "f"(x), "f"(x)); return r;
}
__device__ __forceinline__ float2 unpack2(ULL v) {
    float2 r; asm("mov.b64 {%0, %1}, %2;" : "=f"(r.x), "=f"(r.y) : "l"(v)); return r;
}

// ---------------------------------------------------------------------------
// Kernel 1: fused node GEMMs (q,k,v,skip). 128x128 tile, 512 threads.
// Thread computes 4 rows x 8 cols (acc = 16 ULL = 32 regs) -> fits 62-reg cap
// for 2 blocks/SM = 1024 threads/SM, with headroom for ptxas pipelining.
// ---------------------------------------------------------------------------
#define ASTRIDE 130

__global__ __launch_bounds__(512, 2)
void gemm_qkvs(const float* __restrict__ x, int Nn,
               const float* __restrict__ Wq, const float* __restrict__ bq, float* __restrict__ oq,
               const float* __restrict__ Wk, const float* __restrict__ bk, float* __restrict__ ok,
               const float* __restrict__ Wv, const float* __restrict__ bv, float* __restrict__ ov,
               const float* __restrict__ Ws, const float* __restrict__ bs, float* __restrict__ os)
{
    __shared__ __align__(16) float As[32 * ASTRIDE];   // transposed A: [k][row]
    __shared__ __align__(16) float Bs[32 * 128];

    const float* W; const float* bias; float* out;
    int m = blockIdx.y;
    if (m == 0)      { W = Wq; bias = bq; out = oq; }
    else if (m == 1) { W = Wk; bias = bk; out = ok; }
    else if (m == 2) { W = Wv; bias = bv; out = ov; }
    else             { W = Ws; bias = bs; out = os; }

    int rowBase = blockIdx.x * 128;
    int tid = threadIdx.x;
    int tx = tid & 15;       // col octet: cols [tx*8, tx*8+8)
    int ty = tid >> 4;       // 0..31: rows [ty*4, ty*4+4)

    ULL acc[2][8];           // [rowpair][col]
    #pragma unroll
    for (int i = 0; i < 2; i++)
        #pragma unroll
        for (int j = 0; j < 8; j++) acc[i][j] = 0ull;

    #pragma unroll
    for (int kt = 0; kt < 4; kt++) {
        int k0 = kt * 32;
        // --- load A tile (128 rows x 32 k) transposed: 1024 float4 slots, 2 iters
        #pragma unroll
        for (int it = 0; it < 2; it++) {
            int fi  = tid + it * 512;
            int row = fi >> 3;            // 0..127
            int c4  = fi & 7;             // 0..7
            int gr  = rowBase + row;
            float4 v = make_float4(0.f, 0.f, 0.f, 0.f);
            if (gr < Nn) v = *(const float4*)(x + (size_t)gr * DIN + k0 + c4 * 4);
            As[(c4 * 4 + 0) * ASTRIDE + row] = v.x;
            As[(c4 * 4 + 1) * ASTRIDE + row] = v.y;
            As[(c4 * 4 + 2) * ASTRIDE + row] = v.z;
            As[(c4 * 4 + 3) * ASTRIDE + row] = v.w;
        }
        // --- load B tile (32 k x 128 cols): 1024 float4 slots, 2 iters
        #pragma unroll
        for (int it = 0; it < 2; it++) {
            int fi = tid + it * 512;
            int kk = fi >> 5;             // 0..31
            int c4 = fi & 31;             // 0..31
            *(float4*)(&Bs[kk * 128 + c4 * 4]) =
                *(const float4*)(W + (size_t)(k0 + kk) * HC + c4 * 4);
        }
        __syncthreads();

        #pragma unroll
        for (int k = 0; k < 32; k++) {
            const ULL* ap = (const ULL*)(&As[k * ASTRIDE + ty * 4]);
            ULL a0 = ap[0], a1 = ap[1];          // rows (4ty,4ty+1),(4ty+2,4ty+3)
            float4 b03 = *(const float4*)(&Bs[k * 128 + tx * 8]);
            float4 b47 = *(const float4*)(&Bs[k * 128 + tx * 8 + 4]);
            {   // cols 0..3 (bd staged 4-wide to bound live registers)
                ULL bd0 = packdup(b03.x), bd1 = packdup(b03.y);
                ULL bd2 = packdup(b03.z), bd3 = packdup(b03.w);
                ffma2(acc[0][0], a0, bd0); ffma2(acc[1][0], a1, bd0);
                ffma2(acc[0][1], a0, bd1); ffma2(acc[1][1], a1, bd1);
                ffma2(acc[0][2], a0, bd2); ffma2(acc[1][2], a1, bd2);
                ffma2(acc[0][3], a0, bd3); ffma2(acc[1][3], a1, bd3);
            }
            {   // cols 4..7
                ULL bd4 = packdup(b47.x), bd5 = packdup(b47.y);
                ULL bd6 = packdup(b47.z), bd7 = packdup(b47.w);
                ffma2(acc[0][4], a0, bd4); ffma2(acc[1][4], a1, bd4);
                ffma2(acc[0][5], a0, bd5); ffma2(acc[1][5], a1, bd5);
                ffma2(acc[0][6], a0, bd6); ffma2(acc[1][6], a1, bd6);
                ffma2(acc[0][7], a0, bd7); ffma2(acc[1][7], a1, bd7);
            }
        }
        __syncthreads();
    }

    // --- epilogue: vectorized float4 stores, bias added
    float4 bias03 = __ldg((const float4*)(bias + tx * 8));
    float4 bias47 = __ldg((const float4*)(bias + tx * 8 + 4));
    #pragma unroll
    for (int i = 0; i < 2; i++) {
        float2 u0 = unpack2(acc[i][0]), u1 = unpack2(acc[i][1]);
        float2 u2 = unpack2(acc[i][2]), u3 = unpack2(acc[i][3]);
        float2 u4 = unpack2(acc[i][4]), u5 = unpack2(acc[i][5]);
        float2 u6 = unpack2(acc[i][6]), u7 = unpack2(acc[i][7]);
        int r0 = rowBase + ty * 4 + i * 2;
        if (r0 < Nn) {
            *(float4*)(out + (size_t)r0 * HC + tx * 8) =
                make_float4(u0.x + bias03.x, u1.x + bias03.y, u2.x + bias03.z, u3.x + bias03.w);
            *(float4*)(out + (size_t)r0 * HC + tx * 8 + 4) =
                make_float4(u4.x + bias47.x, u5.x + bias47.y, u6.x + bias47.z, u7.x + bias47.w);
        }
        if (r0 + 1 < Nn) {
            *(float4*)(out + (size_t)(r0 + 1) * HC + tx * 8) =
                make_float4(u0.y + bias03.x, u1.y + bias03.y, u2.y + bias03.z, u3.y + bias03.w);
            *(float4*)(out + (size_t)(r0 + 1) * HC + tx * 8 + 4) =
                make_float4(u4.y + bias47.x, u5.y + bias47.y, u6.y + bias47.z, u7.y + bias47.w);
        }
    }
}

// ---------------------------------------------------------------------------
// Kernel 2: p[n][h*32+d] = sum_{c<64} q[n][h*64+c] * We[d][h*64+c]
// ---------------------------------------------------------------------------
__global__ __launch_bounds__(256)
void p_kernel(const float* __restrict__ gq, const float* __restrict__ We,
              float* __restrict__ gp, int Nn)
{
    __shared__ float Ws[32 * 129];
    for (int i = threadIdx.x; i < ED * HC; i += blockDim.x)
        Ws[(i >> 7) * 129 + (i & 127)] = __ldg(&We[i]);
    __syncthreads();

    int warpId = (blockIdx.x * blockDim.x + threadIdx.x) >> 5;
    int lane   = threadIdx.x & 31;
    int nw     = (gridDim.x * blockDim.x) >> 5;

    for (int n = warpId; n < Nn; n += nw) {
        const float* qb = gq + (size_t)n * HC;
        const float* wrow = &Ws[lane * 129];
        float acc0 = 0.f, acc1 = 0.f;
        #pragma unroll
        for (int c4 = 0; c4 < 16; c4++) {
            float4 qa = *(const float4*)(qb + c4 * 4);
            float4 qc = *(const float4*)(qb + 64 + c4 * 4);
            acc0 += qa.x * wrow[c4 * 4]     + qa.y * wrow[c4 * 4 + 1]
                  + qa.z * wrow[c4 * 4 + 2] + qa.w * wrow[c4 * 4 + 3];
            acc1 += qc.x * wrow[64 + c4 * 4]     + qc.y * wrow[64 + c4 * 4 + 1]
                  + qc.z * wrow[64 + c4 * 4 + 2] + qc.w * wrow[64 + c4 * 4 + 3];
        }
        gp[(size_t)n * 64 + lane]      = acc0;
        gp[(size_t)n * 64 + 32 + lane] = acc1;
    }
}

// ---------------------------------------------------------------------------
// CSR build: histogram -> 3-phase parallel scan -> scatter (int2 stream)
// ---------------------------------------------------------------------------
__global__ void hist_kernel(const int* __restrict__ ei, int* __restrict__ cnt, int E)
{
    int e = blockIdx.x * blockDim.x + threadIdx.x;
    if (e < E) atomicAdd(&cnt[__ldg(&ei[E + e])], 1);
}

__global__ __launch_bounds__(1024)
void scan_block(const int* __restrict__ cnt, int* __restrict__ offs,
                int* __restrict__ bsum, int Nn)
{
    __shared__ int wsum[32];
    int tid = threadIdx.x, lane = tid & 31, wid = tid >> 5;
    int i = blockIdx.x * 1024 + tid;
    int v = (i < Nn) ? cnt[i] : 0;
    int x = v;
    #pragma unroll
    for (int o = 1; o < 32; o <<= 1) {
        int t = __shfl_up_sync(0xffffffffu, x, o);
        if (lane >= o) x += t;
    }
    if (lane == 31) wsum[wid] = x;
    __syncthreads();
    if (wid == 0) {
        int s = wsum[lane];
        #pragma unroll
        for (int o = 1; o < 32; o <<= 1) {
            int t = __shfl_up_sync(0xffffffffu, s, o);
            if (lane >= o) s += t;
        }
        wsum[lane] = s;
    }
    __syncthreads();
    int wbase = (wid == 0) ? 0 : wsum[wid - 1];
    if (i < Nn) offs[i] = wbase + x - v;
    if (tid == 1023) bsum[blockIdx.x] = wsum[31];
}

__global__ void scan_tops(int* __restrict__ bsum, int* __restrict__ offs, int Nn, int nb)
{
    if (threadIdx.x == 0) {
        int run = 0;
        for (int b = 0; b < nb; b++) { int t = bsum[b]; bsum[b] = run; run += t; }
        offs[Nn] = run;
    }
}

__global__ __launch_bounds__(1024)
void scan_add(int* __restrict__ offs, int* __restrict__ curs,
              const int* __restrict__ bsum, int Nn)
{
    int i = blockIdx.x * 1024 + threadIdx.x;
    if (i < Nn) {
        int o = offs[i] + __ldg(&bsum[blockIdx.x]);
        offs[i] = o;
        curs[i] = o;
    }
}

__global__ void scatter_kernel(const int* __restrict__ ei, int* __restrict__ curs,
                               int2* __restrict__ es, int E)
{
    int e = blockIdx.x * blockDim.x + threadIdx.x;
    if (e < E) {
        int d = __ldg(&ei[E + e]);
        int pos = atomicAdd(&curs[d], 1);
        es[pos] = make_int2(e, __ldg(&ei[e]));
    }
}

// ---------------------------------------------------------------------------
// Kernel 3: dst-stationary edge aggregation (R6 measured-best version).
// One warp per dst node. Lane l owns channels [4l, 4l+4); lanes 0-15 head 0,
// 16-31 head 1. Half-warp butterfly reduces both heads in 4 shfls. No atomics.
// ---------------------------------------------------------------------------
__global__ __launch_bounds__(256)
void edge_agg(const int* __restrict__ offs, const int2* __restrict__ es,
              const float* __restrict__ ea,
              const float* __restrict__ gq, const float* __restrict__ gk,
              const float* __restrict__ gv, const float* __restrict__ gp,
              float* __restrict__ gnum, float* __restrict__ gr,
              float* __restrict__ gden, int Nn)
{
    int lane = threadIdx.x & 31;
    int n = blockIdx.x * 8 + (threadIdx.x >> 5);
    if (n >= Nn) return;

    int h = lane >> 4;          // head
    int j = lane & 15;          // lane within head

    int beg = __ldg(&offs[n]);
    int end = __ldg(&offs[n + 1]);

    float4 q4 = __ldg((const float4*)(gq + (size_t)n * HC + 4 * lane));
    float2 p2 = __ldg((const float2*)(gp + (size_t)n * 64 + h * 32 + 2 * j));

    float a0 = 0.f, a1 = 0.f, a2 = 0.f, a3 = 0.f;
    float r0 = 0.f, r1 = 0.f, dw = 0.f;

    int i = beg;
    for (; i + 2 <= end; i += 2) {
        int2 eA = __ldg(&es[i]);
        int2 eB = __ldg(&es[i + 1]);
        float4 kA = __ldg((const float4*)(gk + (size_t)eA.y * HC + 4 * lane));
        float4 kB = __ldg((const float4*)(gk + (size_t)eB.y * HC + 4 * lane));
        float4 vA = __ldg((const float4*)(gv + (size_t)eA.y * HC + 4 * lane));
        float4 vB = __ldg((const float4*)(gv + (size_t)eB.y * HC + 4 * lane));
        float2 cA = __ldg((const float2*)(ea + (size_t)eA.x * ED + 2 * j));
        float2 cB = __ldg((const float2*)(ea + (size_t)eB.x * ED + 2 * j));

        float sA = q4.x * kA.x + q4.y * kA.y + q4.z * kA.z + q4.w * kA.w
                 + cA.x * p2.x + cA.y * p2.y;
        float sB = q4.x * kB.x + q4.y * kB.y + q4.z * kB.z + q4.w * kB.w
                 + cB.x * p2.x + cB.y * p2.y;
        #pragma unroll
        for (int o = 8; o > 0; o >>= 1) {
            sA += __shfl_xor_sync(0xffffffffu, sA, o);
            sB += __shfl_xor_sync(0xffffffffu, sB, o);
        }
        float wA = __expf(sA * 0.125f);   // 1/sqrt(64)
        float wB = __expf(sB * 0.125f);

        a0 += wA * vA.x + wB * vB.x;
        a1 += wA * vA.y + wB * vB.y;
        a2 += wA * vA.z + wB * vB.z;
        a3 += wA * vA.w + wB * vB.w;
        r0 += wA * cA.x + wB * cB.x;
        r1 += wA * cA.y + wB * cB.y;
        dw += wA + wB;
    }
    if (i < end) {
        int2 eA = __ldg(&es[i]);
        float4 kA = __ldg((const float4*)(gk + (size_t)eA.y * HC + 4 * lane));
        float4 vA = __ldg((const float4*)(gv + (size_t)eA.y * HC + 4 * lane));
        float2 cA = __ldg((const float2*)(ea + (size_t)eA.x * ED + 2 * j));
        float sA = q4.x * kA.x + q4.y * kA.y + q4.z * kA.z + q4.w * kA.w
                 + cA.x * p2.x + cA.y * p2.y;
        #pragma unroll
        for (int o = 8; o > 0; o >>= 1)
            sA += __shfl_xor_sync(0xffffffffu, sA, o);
        float wA = __expf(sA * 0.125f);
        a0 += wA * vA.x; a1 += wA * vA.y; a2 += wA * vA.z; a3 += wA * vA.w;
        r0 += wA * cA.x; r1 += wA * cA.y;
        dw += wA;
    }

    *(float4*)(gnum + (size_t)n * HC + 4 * lane) = make_float4(a0, a1, a2, a3);
    *(float2*)(gr + (size_t)n * 64 + h * 32 + 2 * j) = make_float2(r0, r1);
    if (j == 0) gden[2 * n + h] = dw;
}

// ---------------------------------------------------------------------------
// Kernel 4: finalize as FFMA2 GEMM.
//   rW = r[N,64] @ Bblk[64,128]  (Bblk = block-diag of We halves)
//   out[n][c] += (num[n][c] + rW[n][c]) / (den[n][h] + 1e-16)
// ---------------------------------------------------------------------------
__global__ __launch_bounds__(256, 2)
void finalize_gemm(const float* __restrict__ r, const float* __restrict__ num,
                   const float* __restrict__ den, const float* __restrict__ We,
                   float* __restrict__ out, int Nn)
{
    __shared__ __align__(16) float As[32 * ASTRIDE];
    __shared__ __align__(16) float Bs[32 * 128];

    int rowBase = blockIdx.x * 128;
    int tid = threadIdx.x;
    int tx = tid & 15;
    int ty = tid >> 4;

    ULL acc[4][8];
    #pragma unroll
    for (int i = 0; i < 4; i++)
        #pragma unroll
        for (int j = 0; j < 8; j++) acc[i][j] = 0ull;

    #pragma unroll
    for (int kt = 0; kt < 2; kt++) {
        int k0 = kt * 32;
        #pragma unroll
        for (int it = 0; it < 4; it++) {
            int fi  = tid + it * 256;
            int row = fi >> 3;
            int c4  = fi & 7;
            int gr  = rowBase + row;
            float4 v = make_float4(0.f, 0.f, 0.f, 0.f);
            if (gr < Nn) v = *(const float4*)(r + (size_t)gr * 64 + k0 + c4 * 4);
            As[(c4 * 4 + 0) * ASTRIDE + row] = v.x;
            As[(c4 * 4 + 1) * ASTRIDE + row] = v.y;
            As[(c4 * 4 + 2) * ASTRIDE + row] = v.z;
            As[(c4 * 4 + 3) * ASTRIDE + row] = v.w;
        }
        #pragma unroll
        for (int it = 0; it < 4; it++) {
            int fi = tid + it * 256;
            int kk = fi >> 5;
            int c  = (fi & 31) * 4;
            int d  = k0 + kk;
            float4 w = make_float4(0.f, 0.f, 0.f, 0.f);
            if (d < 32) {
                if (c < 64) w = *(const float4*)(We + (size_t)d * HC + c);
            } else {
                if (c >= 64) w = *(const float4*)(We + (size_t)(d - 32) * HC + c);
            }
            *(float4*)(&Bs[kk * 128 + c]) = w;
        }
        __syncthreads();

        #pragma unroll
        for (int k = 0; k < 32; k++) {
            const ULL* ap = (const ULL*)(&As[k * ASTRIDE + ty * 8]);
            ULL a0 = ap[0], a1 = ap[1], a2 = ap[2], a3 = ap[3];
            float4 b03 = *(const float4*)(&Bs[k * 128 + tx * 8]);
            float4 b47 = *(const float4*)(&Bs[k * 128 + tx * 8 + 4]);
            ULL bd[8];
            bd[0] = packdup(b03.x); bd[1] = packdup(b03.y);
            bd[2] = packdup(b03.z); bd[3] = packdup(b03.w);
            bd[4] = packdup(b47.x); bd[5] = packdup(b47.y);
            bd[6] = packdup(b47.z); bd[7] = packdup(b47.w);
            #pragma unroll
            for (int j = 0; j < 8; j++) {
                ffma2(acc[0][j], a0, bd[j]);
                ffma2(acc[1][j], a1, bd[j]);
                ffma2(acc[2][j], a2, bd[j]);
                ffma2(acc[3][j], a3, bd[j]);
            }
        }
        __syncthreads();
    }

    #pragma unroll
    for (int j = 0; j < 8; j++) {
        int col = tx * 8 + j;
        int h   = col >> 6;
        #pragma unroll
        for (int i2 = 0; i2 < 4; i2++) {
            float2 v = unpack2(acc[i2][j]);
            int gr = rowBase + ty * 8 + i2 * 2;
            if (gr < Nn) {
                float inv = 1.0f / (__ldg(den + 2 * gr + h) + 1e-16f);
                out[(size_t)gr * HC + col] += (num[(size_t)gr * HC + col] + v.x) * inv;
            }
            if (gr + 1 < Nn) {
                float inv = 1.0f / (__ldg(den + 2 * (gr + 1) + h) + 1e-16f);
                out[(size_t)(gr + 1) * HC + col] += (num[(size_t)(gr + 1) * HC + col] + v.y) * inv;
            }
        }
    }
}

// ---------------------------------------------------------------------------
// Launch. gemm_qkvs kept as 4th kernel launch (ncu capture slot).
// ---------------------------------------------------------------------------
extern "C" void kernel_launch(void* const* d_in, const int* in_sizes, int n_in,
                              void* d_out, int out_size)
{
    const float* x     = (const float*)d_in[0];
    const int*   ei    = (const int*)d_in[1];
    const float* ea    = (const float*)d_in[2];
    const float* Wq    = (const float*)d_in[3];
    const float* bq    = (const float*)d_in[4];
    const float* Wk    = (const float*)d_in[5];
    const float* bk    = (const float*)d_in[6];
    const float* Wv    = (const float*)d_in[7];
    const float* bv    = (const float*)d_in[8];
    const float* We    = (const float*)d_in[9];
    const float* Wsk   = (const float*)d_in[10];
    const float* bsk   = (const float*)d_in[11];
    float*       out   = (float*)d_out;

    int Nn = in_sizes[0] / DIN;
    int E  = in_sizes[1] / 2;

    float* base = nullptr;
    cudaGetSymbolAddress((void**)&base, g_buf);
    float* gq   = base + OFF_Q;
    float* gk   = base + OFF_K;
    float* gv   = base + OFF_V;
    float* gp   = base + OFF_P;
    float* gnum = base + OFF_NUM;
    float* gr   = base + OFF_R;
    float* gden = base + OFF_DEN;
    int*   cnt  = (int*)(base + OFF_CNT);
    int*   offs = (int*)(base + OFF_OFFS);
    int*   curs = (int*)(base + OFF_CURS);
    int2*  es   = (int2*)(base + OFF_ES);
    int*   bsum = (int*)(base + OFF_BSUM);

    int eb = (E + 255) / 256;
    int nb = (Nn + 1023) / 1024;

    // zero only the degree histogram
    cudaMemsetAsync(cnt, 0, (size_t)Nn * sizeof(int), 0);

    // K1-K3: CSR front half
    hist_kernel<<<eb, 256>>>(ei, cnt, E);
    scan_block<<<nb, 1024>>>(cnt, offs, bsum, Nn);
    scan_tops<<<1, 32>>>(bsum, offs, Nn, nb);

    // K4 (ncu capture slot): node GEMMs
    dim3 ggrid((Nn + 127) / 128, 4);
    gemm_qkvs<<<ggrid, 512>>>(x, Nn,
                              Wq, bq, gq,
                              Wk, bk, gk,
                              Wv, bv, gv,
                              Wsk, bsk, out);

    // K5-K6: CSR back half
    scan_add<<<nb, 1024>>>(offs, curs, bsum, Nn);
    scatter_kernel<<<eb, 256>>>(ei, curs, es, E);

    // K7: p = q contracted with We (per head)
    p_kernel<<<1480, 256>>>(gq, We, gp, Nn);

    // K8: dst-stationary aggregation (no atomics)
    edge_agg<<<(Nn + 7) / 8, 256>>>(offs, es, ea, gq, gk, gv, gp,
                                    gnum, gr, gden, Nn);

    // K9: finalize: rW GEMM + normalize + skip
    finalize_gemm<<<(Nn + 127) / 128, 256>>>(gr, gnum, gden, We, out, Nn);
}

// round 11
// speedup vs baseline: 1.8658x; 1.3987x over previous
#include <cuda_runtime.h>
#include <cuda_bf16.h>
#include <cstdint>

// Problem constants (fixed by the dataset)
#define NN 50000
#define EE 800000
#define DIN 128
#define HC 128      // H*C
#define CC 64       // per-head channels
#define HH 2
#define ED 32

typedef unsigned long long ULL;

// ---------------------------------------------------------------------------
// Scratch layout (floats). int/bf16 regions aliased.
// ---------------------------------------------------------------------------
#define OFF_Q    ((size_t)0)
#define OFF_K    ((size_t)6400000)
#define OFF_V    ((size_t)12800000)
#define OFF_P    ((size_t)19200000)
#define OFF_NUM  ((size_t)22400000)
#define OFF_R    ((size_t)28800000)
#define OFF_DEN  ((size_t)32000000)
#define OFF_CNT  ((size_t)32100000)
#define OFF_OFFS ((size_t)32160000)
#define OFF_CURS ((size_t)32220000)
#define OFF_ES   ((size_t)32280000)   // int2 per edge (e, src)
#define OFF_BSUM ((size_t)33880000)
#define OFF_XHI  ((size_t)33900000)   // Nn*128 bf16
#define OFF_XLO  ((size_t)37100000)   // Nn*128 bf16
#define OFF_WT   ((size_t)40300000)   // 8*16384 bf16 (4 weights x hi/lo), [n][k]
#define BUF_TOTAL ((size_t)40400000)

__device__ float g_buf[BUF_TOTAL];

// ---------------------------------------------------------------------------
// Packed fp32x2 helpers (finalize GEMM)
// ---------------------------------------------------------------------------
__device__ __forceinline__ void ffma2(ULL &d, ULL a, ULL b) {
    asm volatile("fma.rn.f32x2 %0, %1, %2, %3;" : "=l"(d) : "l"(a), "l"(b), "l"(d));
}
__device__ __forceinline__ ULL packdup(float x) {
    ULL r; asm("mov.b64 %0, {%1, %2};" : "=l"(r) : "f"(x), "f"(x)); return r;
}
__device__ __forceinline__ float2 unpack2(ULL v) {
    float2 r; asm("mov.b64 {%0, %1}, %2;" : "=f"(r.x), "=f"(r.y) : "l"(v)); return r;
}

__device__ __forceinline__ uint32_t smem_u32(const void* p) {
    uint32_t a;
    asm("{ .reg .u64 t; cvta.to.shared.u64 t, %1; cvt.u32.u64 %0, t; }"
        : "=r"(a) : "l"(p));
    return a;
}

// ---------------------------------------------------------------------------
// mma.sync helpers (base-target instructions; no 'a' features)
// ---------------------------------------------------------------------------
__device__ __forceinline__ void ldmatrix_x4(uint32_t* r, uint32_t addr) {
    asm volatile("ldmatrix.sync.aligned.m8n8.x4.shared.b16 {%0,%1,%2,%3}, [%4];"
                 : "=r"(r[0]), "=r"(r[1]), "=r"(r[2]), "=r"(r[3]) : "r"(addr));
}
__device__ __forceinline__ void mma_bf16(float* c, const uint32_t* a,
                                         uint32_t b0, uint32_t b1) {
    asm volatile(
        "mma.sync.aligned.m16n8k16.row.col.f32.bf16.bf16.f32 "
        "{%0,%1,%2,%3}, {%4,%5,%6,%7}, {%8,%9}, {%0,%1,%2,%3};"
        : "+f"(c[0]), "+f"(c[1]), "+f"(c[2]), "+f"(c[3])
        : "r"(a[0]), "r"(a[1]), "r"(a[2]), "r"(a[3]), "r"(b0), "r"(b1));
}

// ---------------------------------------------------------------------------
// Prep kernels: split x into bf16 hi/lo; build transposed bf16 hi/lo weights.
// ---------------------------------------------------------------------------
__global__ void split_x(const float* __restrict__ x, __nv_bfloat16* __restrict__ xhi,
                        __nv_bfloat16* __restrict__ xlo, int n4)
{
    int i = blockIdx.x * blockDim.x + threadIdx.x;
    if (i >= n4) return;
    float4 v = __ldg((const float4*)x + i);
    __nv_bfloat16 h0 = __float2bfloat16(v.x), h1 = __float2bfloat16(v.y);
    __nv_bfloat16 h2 = __float2bfloat16(v.z), h3 = __float2bfloat16(v.w);
    __nv_bfloat16 l0 = __float2bfloat16(v.x - __bfloat162float(h0));
    __nv_bfloat16 l1 = __float2bfloat16(v.y - __bfloat162float(h1));
    __nv_bfloat16 l2 = __float2bfloat16(v.z - __bfloat162float(h2));
    __nv_bfloat16 l3 = __float2bfloat16(v.w - __bfloat162float(h3));
    __nv_bfloat162* ph = (__nv_bfloat162*)xhi;
    __nv_bfloat162* pl = (__nv_bfloat162*)xlo;
    ph[i * 2]     = __nv_bfloat162(h0, h1);
    ph[i * 2 + 1] = __nv_bfloat162(h2, h3);
    pl[i * 2]     = __nv_bfloat162(l0, l1);
    pl[i * 2 + 1] = __nv_bfloat162(l2, l3);
}

__global__ void prep_w(const float* __restrict__ Wq, const float* __restrict__ Wk,
                       const float* __restrict__ Wv, const float* __restrict__ Ws,
                       __nv_bfloat16* __restrict__ wt)
{
    int m = blockIdx.y;
    const float* W = (m == 0) ? Wq : (m == 1) ? Wk : (m == 2) ? Wv : Ws;
    int idx = blockIdx.x * 256 + threadIdx.x;
    if (idx >= 16384) return;
    int n = idx >> 7, k = idx & 127;
    float v = __ldg(&W[k * 128 + n]);        // transpose: wt[n][k] = W[k][n]
    __nv_bfloat16 h = __float2bfloat16(v);
    __nv_bfloat16 l = __float2bfloat16(v - __bfloat162float(h));
    wt[m * 16384 + idx]         = h;
    wt[65536 + m * 16384 + idx] = l;
}

// ---------------------------------------------------------------------------
// mma.sync GEMM: out = x @ W + bias, split-bf16 3-term.
// 128x128 tile/CTA, 256 threads = 8 warps (4 M x 2 N); warp = 32x64.
// Smem tiles row-padded to 272B (bank-conflict-free ldmatrix, no swizzle).
// ---------------------------------------------------------------------------
#define RS 272                         // row stride in bytes (136 bf16)
#define TILE_BYTES (128 * RS)          // 34816
#define SMEM_MMA_BYTES (4 * TILE_BYTES)

__global__ __launch_bounds__(256, 1)
void gemm_mma(const __nv_bfloat16* __restrict__ xhi, const __nv_bfloat16* __restrict__ xlo,
              const __nv_bfloat16* __restrict__ wt,
              const float* __restrict__ bq, const float* __restrict__ bk,
              const float* __restrict__ bv, const float* __restrict__ bs,
              float* __restrict__ oq, float* __restrict__ ok,
              float* __restrict__ ov, float* __restrict__ os, int Nn)
{
    extern __shared__ __align__(16) char smem[];
    uint32_t sA  = smem_u32(smem);                 // Ahi
    uint32_t sAl = sA + TILE_BYTES;                // Alo
    uint32_t sB  = sA + 2 * TILE_BYTES;            // Bhi
    uint32_t sBl = sA + 3 * TILE_BYTES;            // Blo

    int tid  = threadIdx.x;
    int wid  = tid >> 5;
    int lane = tid & 31;
    int m    = blockIdx.y;
    int rowBase = blockIdx.x * 128;

    const float* bias = (m == 0) ? bq : (m == 1) ? bk : (m == 2) ? bv : bs;
    float* out        = (m == 0) ? oq : (m == 1) ? ok : (m == 2) ? ov : os;
    const __nv_bfloat16* wth = wt + m * 16384;
    const __nv_bfloat16* wtl = wt + 65536 + m * 16384;

    // ---- load tiles: each tile 128 rows x 256B, 16 uint4/row -> 2048 uint4
    #pragma unroll
    for (int t = 0; t < 4; t++) {
        const __nv_bfloat16* g = (t == 0) ? xhi : (t == 1) ? xlo : (t == 2) ? wth : wtl;
        uint32_t sdst = sA + t * TILE_BYTES;
        bool isA = (t < 2);
        #pragma unroll
        for (int it = 0; it < 8; it++) {
            int idx = tid + it * 256;
            int row = idx >> 4;
            int c16 = idx & 15;
            uint4 v = make_uint4(0u, 0u, 0u, 0u);
            if (!isA) {
                v = *(const uint4*)(g + (size_t)row * 128 + c16 * 8);
            } else {
                int gr = rowBase + row;
                if (gr < Nn) v = *(const uint4*)(g + (size_t)gr * 128 + c16 * 8);
            }
            asm volatile("st.shared.v4.b32 [%0], {%1, %2, %3, %4};"
                         :: "r"(sdst + (uint32_t)row * RS + (uint32_t)c16 * 16),
                            "r"(v.x), "r"(v.y), "r"(v.z), "r"(v.w));
        }
    }
    __syncthreads();

    int wm = wid & 3;        // M quadrant: rows wm*32
    int wn = wid >> 2;       // N half:    cols wn*64

    // ldmatrix per-lane addressing
    // A (x4): m0..m3 = {rows 0-7, rows 8-15} x {k 0-7, k 8-15}
    uint32_t aRow = (uint32_t)((lane & 7) + ((lane & 8) ? 8 : 0));
    uint32_t aKb  = (lane & 16) ? 16u : 0u;
    uint32_t aBaseH = sA  + (uint32_t)(wm * 32 + aRow) * RS + aKb;
    uint32_t aBaseL = sAl + (uint32_t)(wm * 32 + aRow) * RS + aKb;
    // B (x4): m0,m1 = n-tile nt {k 0-7, k 8-15}; m2,m3 = n-tile nt+1
    uint32_t bRow = (uint32_t)((lane & 7) + ((lane & 16) ? 8 : 0));
    uint32_t bKb  = (lane & 8) ? 16u : 0u;
    uint32_t bBaseH = sB  + (uint32_t)(wn * 64 + bRow) * RS + bKb;
    uint32_t bBaseL = sBl + (uint32_t)(wn * 64 + bRow) * RS + bKb;

    float acc[2][8][4];
    #pragma unroll
    for (int mt = 0; mt < 2; mt++)
        #pragma unroll
        for (int nt = 0; nt < 8; nt++)
            #pragma unroll
            for (int c = 0; c < 4; c++) acc[mt][nt][c] = 0.f;

    #pragma unroll
    for (int ks = 0; ks < 8; ks++) {
        uint32_t ko = (uint32_t)ks * 32;
        uint32_t ah[2][4], al[2][4];
        ldmatrix_x4(ah[0], aBaseH + ko);
        ldmatrix_x4(ah[1], aBaseH + 16 * RS + ko);
        ldmatrix_x4(al[0], aBaseL + ko);
        ldmatrix_x4(al[1], aBaseL + 16 * RS + ko);
        #pragma unroll
        for (int np = 0; np < 4; np++) {      // n-tile pair (2*np, 2*np+1)
            uint32_t bh[4], bl[4];
            ldmatrix_x4(bh, bBaseH + (uint32_t)(np * 16) * RS + ko);
            ldmatrix_x4(bl, bBaseL + (uint32_t)(np * 16) * RS + ko);
            #pragma unroll
            for (int mt = 0; mt < 2; mt++) {
                mma_bf16(acc[mt][2 * np],     ah[mt], bh[0], bh[1]);
                mma_bf16(acc[mt][2 * np + 1], ah[mt], bh[2], bh[3]);
                mma_bf16(acc[mt][2 * np],     ah[mt], bl[0], bl[1]);
                mma_bf16(acc[mt][2 * np + 1], ah[mt], bl[2], bl[3]);
                mma_bf16(acc[mt][2 * np],     al[mt], bh[0], bh[1]);
                mma_bf16(acc[mt][2 * np + 1], al[mt], bh[2], bh[3]);
            }
        }
    }

    // ---- epilogue: C frag: c0=C[g][2t], c1=C[g][2t+1], c2=C[g+8][2t], c3=..
    int g8 = lane >> 2;
    int tq = lane & 3;
    #pragma unroll
    for (int nt = 0; nt < 8; nt++) {
        int col = wn * 64 + nt * 8 + 2 * tq;
        float2 b2 = __ldg((const float2*)(bias + col));
        #pragma unroll
        for (int mt = 0; mt < 2; mt++) {
            int r0 = rowBase + wm * 32 + mt * 16 + g8;
            if (r0 < Nn)
                *(float2*)(out + (size_t)r0 * HC + col) =
                    make_float2(acc[mt][nt][0] + b2.x, acc[mt][nt][1] + b2.y);
            if (r0 + 8 < Nn)
                *(float2*)(out + (size_t)(r0 + 8) * HC + col) =
                    make_float2(acc[mt][nt][2] + b2.x, acc[mt][nt][3] + b2.y);
        }
    }
}

// ---------------------------------------------------------------------------
// Kernel 2: p[n][h*32+d] = sum_{c<64} q[n][h*64+c] * We[d][h*64+c]
// ---------------------------------------------------------------------------
__global__ __launch_bounds__(256)
void p_kernel(const float* __restrict__ gq, const float* __restrict__ We,
              float* __restrict__ gp, int Nn)
{
    __shared__ float Ws[32 * 129];
    for (int i = threadIdx.x; i < ED * HC; i += blockDim.x)
        Ws[(i >> 7) * 129 + (i & 127)] = __ldg(&We[i]);
    __syncthreads();

    int warpId = (blockIdx.x * blockDim.x + threadIdx.x) >> 5;
    int lane   = threadIdx.x & 31;
    int nw     = (gridDim.x * blockDim.x) >> 5;

    for (int n = warpId; n < Nn; n += nw) {
        const float* qb = gq + (size_t)n * HC;
        const float* wrow = &Ws[lane * 129];
        float acc0 = 0.f, acc1 = 0.f;
        #pragma unroll
        for (int c4 = 0; c4 < 16; c4++) {
            float4 qa = *(const float4*)(qb + c4 * 4);
            float4 qc = *(const float4*)(qb + 64 + c4 * 4);
            acc0 += qa.x * wrow[c4 * 4]     + qa.y * wrow[c4 * 4 + 1]
                  + qa.z * wrow[c4 * 4 + 2] + qa.w * wrow[c4 * 4 + 3];
            acc1 += qc.x * wrow[64 + c4 * 4]     + qc.y * wrow[64 + c4 * 4 + 1]
                  + qc.z * wrow[64 + c4 * 4 + 2] + qc.w * wrow[64 + c4 * 4 + 3];
        }
        gp[(size_t)n * 64 + lane]      = acc0;
        gp[(size_t)n * 64 + 32 + lane] = acc1;
    }
}

// ---------------------------------------------------------------------------
// CSR build: histogram -> 3-phase parallel scan -> scatter (int2 stream)
// ---------------------------------------------------------------------------
__global__ void hist_kernel(const int* __restrict__ ei, int* __restrict__ cnt, int E)
{
    int e = blockIdx.x * blockDim.x + threadIdx.x;
    if (e < E) atomicAdd(&cnt[__ldg(&ei[E + e])], 1);
}

__global__ __launch_bounds__(1024)
void scan_block(const int* __restrict__ cnt, int* __restrict__ offs,
                int* __restrict__ bsum, int Nn)
{
    __shared__ int wsum[32];
    int tid = threadIdx.x, lane = tid & 31, wid = tid >> 5;
    int i = blockIdx.x * 1024 + tid;
    int v = (i < Nn) ? cnt[i] : 0;
    int x = v;
    #pragma unroll
    for (int o = 1; o < 32; o <<= 1) {
        int t = __shfl_up_sync(0xffffffffu, x, o);
        if (lane >= o) x += t;
    }
    if (lane == 31) wsum[wid] = x;
    __syncthreads();
    if (wid == 0) {
        int s = wsum[lane];
        #pragma unroll
        for (int o = 1; o < 32; o <<= 1) {
            int t = __shfl_up_sync(0xffffffffu, s, o);
            if (lane >= o) s += t;
        }
        wsum[lane] = s;
    }
    __syncthreads();
    int wbase = (wid == 0) ? 0 : wsum[wid - 1];
    if (i < Nn) offs[i] = wbase + x - v;
    if (tid == 1023) bsum[blockIdx.x] = wsum[31];
}

__global__ void scan_tops(int* __restrict__ bsum, int* __restrict__ offs, int Nn, int nb)
{
    if (threadIdx.x == 0) {
        int run = 0;
        for (int b = 0; b < nb; b++) { int t = bsum[b]; bsum[b] = run; run += t; }
        offs[Nn] = run;
    }
}

__global__ __launch_bounds__(1024)
void scan_add(int* __restrict__ offs, int* __restrict__ curs,
              const int* __restrict__ bsum, int Nn)
{
    int i = blockIdx.x * 1024 + threadIdx.x;
    if (i < Nn) {
        int o = offs[i] + __ldg(&bsum[blockIdx.x]);
        offs[i] = o;
        curs[i] = o;
    }
}

__global__ void scatter_kernel(const int* __restrict__ ei, int* __restrict__ curs,
                               int2* __restrict__ es, int E)
{
    int e = blockIdx.x * blockDim.x + threadIdx.x;
    if (e < E) {
        int d = __ldg(&ei[E + e]);
        int pos = atomicAdd(&curs[d], 1);
        es[pos] = make_int2(e, __ldg(&ei[e]));
    }
}

// ---------------------------------------------------------------------------
// Kernel 3: dst-stationary edge aggregation (measured-best R6 version).
// ---------------------------------------------------------------------------
__global__ __launch_bounds__(256)
void edge_agg(const int* __restrict__ offs, const int2* __restrict__ es,
              const float* __restrict__ ea,
              const float* __restrict__ gq, const float* __restrict__ gk,
              const float* __restrict__ gv, const float* __restrict__ gp,
              float* __restrict__ gnum, float* __restrict__ gr,
              float* __restrict__ gden, int Nn)
{
    int lane = threadIdx.x & 31;
    int n = blockIdx.x * 8 + (threadIdx.x >> 5);
    if (n >= Nn) return;

    int h = lane >> 4;
    int j = lane & 15;

    int beg = __ldg(&offs[n]);
    int end = __ldg(&offs[n + 1]);

    float4 q4 = __ldg((const float4*)(gq + (size_t)n * HC + 4 * lane));
    float2 p2 = __ldg((const float2*)(gp + (size_t)n * 64 + h * 32 + 2 * j));

    float a0 = 0.f, a1 = 0.f, a2 = 0.f, a3 = 0.f;
    float r0 = 0.f, r1 = 0.f, dw = 0.f;

    int i = beg;
    for (; i + 2 <= end; i += 2) {
        int2 eA = __ldg(&es[i]);
        int2 eB = __ldg(&es[i + 1]);
        float4 kA = __ldg((const float4*)(gk + (size_t)eA.y * HC + 4 * lane));
        float4 kB = __ldg((const float4*)(gk + (size_t)eB.y * HC + 4 * lane));
        float4 vA = __ldg((const float4*)(gv + (size_t)eA.y * HC + 4 * lane));
        float4 vB = __ldg((const float4*)(gv + (size_t)eB.y * HC + 4 * lane));
        float2 cA = __ldg((const float2*)(ea + (size_t)eA.x * ED + 2 * j));
        float2 cB = __ldg((const float2*)(ea + (size_t)eB.x * ED + 2 * j));

        float sA = q4.x * kA.x + q4.y * kA.y + q4.z * kA.z + q4.w * kA.w
                 + cA.x * p2.x + cA.y * p2.y;
        float sB = q4.x * kB.x + q4.y * kB.y + q4.z * kB.z + q4.w * kB.w
                 + cB.x * p2.x + cB.y * p2.y;
        #pragma unroll
        for (int o = 8; o > 0; o >>= 1) {
            sA += __shfl_xor_sync(0xffffffffu, sA, o);
            sB += __shfl_xor_sync(0xffffffffu, sB, o);
        }
        float wA = __expf(sA * 0.125f);
        float wB = __expf(sB * 0.125f);

        a0 += wA * vA.x + wB * vB.x;
        a1 += wA * vA.y + wB * vB.y;
        a2 += wA * vA.z + wB * vB.z;
        a3 += wA * vA.w + wB * vB.w;
        r0 += wA * cA.x + wB * cB.x;
        r1 += wA * cA.y + wB * cB.y;
        dw += wA + wB;
    }
    if (i < end) {
        int2 eA = __ldg(&es[i]);
        float4 kA = __ldg((const float4*)(gk + (size_t)eA.y * HC + 4 * lane));
        float4 vA = __ldg((const float4*)(gv + (size_t)eA.y * HC + 4 * lane));
        float2 cA = __ldg((const float2*)(ea + (size_t)eA.x * ED + 2 * j));
        float sA = q4.x * kA.x + q4.y * kA.y + q4.z * kA.z + q4.w * kA.w
                 + cA.x * p2.x + cA.y * p2.y;
        #pragma unroll
        for (int o = 8; o > 0; o >>= 1)
            sA += __shfl_xor_sync(0xffffffffu, sA, o);
        float wA = __expf(sA * 0.125f);
        a0 += wA * vA.x; a1 += wA * vA.y; a2 += wA * vA.z; a3 += wA * vA.w;
        r0 += wA * cA.x; r1 += wA * cA.y;
        dw += wA;
    }

    *(float4*)(gnum + (size_t)n * HC + 4 * lane) = make_float4(a0, a1, a2, a3);
    *(float2*)(gr + (size_t)n * 64 + h * 32 + 2 * j) = make_float2(r0, r1);
    if (j == 0) gden[2 * n + h] = dw;
}

// ---------------------------------------------------------------------------
// Kernel 4: finalize as FFMA2 GEMM (rW = r @ Bblk; normalize; add skip).
// ---------------------------------------------------------------------------
#define ASTRIDE 130

__global__ __launch_bounds__(256, 2)
void finalize_gemm(const float* __restrict__ r, const float* __restrict__ num,
                   const float* __restrict__ den, const float* __restrict__ We,
                   float* __restrict__ out, int Nn)
{
    __shared__ __align__(16) float As[32 * ASTRIDE];
    __shared__ __align__(16) float Bs[32 * 128];

    int rowBase = blockIdx.x * 128;
    int tid = threadIdx.x;
    int tx = tid & 15;
    int ty = tid >> 4;

    ULL acc[4][8];
    #pragma unroll
    for (int i = 0; i < 4; i++)
        #pragma unroll
        for (int j = 0; j < 8; j++) acc[i][j] = 0ull;

    #pragma unroll
    for (int kt = 0; kt < 2; kt++) {
        int k0 = kt * 32;
        #pragma unroll
        for (int it = 0; it < 4; it++) {
            int fi  = tid + it * 256;
            int row = fi >> 3;
            int c4  = fi & 7;
            int gr  = rowBase + row;
            float4 v = make_float4(0.f, 0.f, 0.f, 0.f);
            if (gr < Nn) v = *(const float4*)(r + (size_t)gr * 64 + k0 + c4 * 4);
            As[(c4 * 4 + 0) * ASTRIDE + row] = v.x;
            As[(c4 * 4 + 1) * ASTRIDE + row] = v.y;
            As[(c4 * 4 + 2) * ASTRIDE + row] = v.z;
            As[(c4 * 4 + 3) * ASTRIDE + row] = v.w;
        }
        #pragma unroll
        for (int it = 0; it < 4; it++) {
            int fi = tid + it * 256;
            int kk = fi >> 5;
            int c  = (fi & 31) * 4;
            int d  = k0 + kk;
            float4 w = make_float4(0.f, 0.f, 0.f, 0.f);
            if (d < 32) {
                if (c < 64) w = *(const float4*)(We + (size_t)d * HC + c);
            } else {
                if (c >= 64) w = *(const float4*)(We + (size_t)(d - 32) * HC + c);
            }
            *(float4*)(&Bs[kk * 128 + c]) = w;
        }
        __syncthreads();

        #pragma unroll
        for (int k = 0; k < 32; k++) {
            const ULL* ap = (const ULL*)(&As[k * ASTRIDE + ty * 8]);
            ULL a0 = ap[0], a1 = ap[1], a2 = ap[2], a3 = ap[3];
            float4 b03 = *(const float4*)(&Bs[k * 128 + tx * 8]);
            float4 b47 = *(const float4*)(&Bs[k * 128 + tx * 8 + 4]);
            ULL bd[8];
            bd[0] = packdup(b03.x); bd[1] = packdup(b03.y);
            bd[2] = packdup(b03.z); bd[3] = packdup(b03.w);
            bd[4] = packdup(b47.x); bd[5] = packdup(b47.y);
            bd[6] = packdup(b47.z); bd[7] = packdup(b47.w);
            #pragma unroll
            for (int j = 0; j < 8; j++) {
                ffma2(acc[0][j], a0, bd[j]);
                ffma2(acc[1][j], a1, bd[j]);
                ffma2(acc[2][j], a2, bd[j]);
                ffma2(acc[3][j], a3, bd[j]);
            }
        }
        __syncthreads();
    }

    #pragma unroll
    for (int j = 0; j < 8; j++) {
        int col = tx * 8 + j;
        int h   = col >> 6;
        #pragma unroll
        for (int i2 = 0; i2 < 4; i2++) {
            float2 v = unpack2(acc[i2][j]);
            int gr = rowBase + ty * 8 + i2 * 2;
            if (gr < Nn) {
                float inv = 1.0f / (__ldg(den + 2 * gr + h) + 1e-16f);
                out[(size_t)gr * HC + col] += (num[(size_t)gr * HC + col] + v.x) * inv;
            }
            if (gr + 1 < Nn) {
                float inv = 1.0f / (__ldg(den + 2 * (gr + 1) + h) + 1e-16f);
                out[(size_t)(gr + 1) * HC + col] += (num[(size_t)(gr + 1) * HC + col] + v.y) * inv;
            }
        }
    }
}

// ---------------------------------------------------------------------------
// Launch. gemm_mma is the 4th kernel (ncu capture slot).
// ---------------------------------------------------------------------------
extern "C" void kernel_launch(void* const* d_in, const int* in_sizes, int n_in,
                              void* d_out, int out_size)
{
    const float* x     = (const float*)d_in[0];
    const int*   ei    = (const int*)d_in[1];
    const float* ea    = (const float*)d_in[2];
    const float* Wq    = (const float*)d_in[3];
    const float* bq    = (const float*)d_in[4];
    const float* Wk    = (const float*)d_in[5];
    const float* bk    = (const float*)d_in[6];
    const float* Wv    = (const float*)d_in[7];
    const float* bv    = (const float*)d_in[8];
    const float* We    = (const float*)d_in[9];
    const float* Wsk   = (const float*)d_in[10];
    const float* bsk   = (const float*)d_in[11];
    float*       out   = (float*)d_out;

    int Nn = in_sizes[0] / DIN;
    int E  = in_sizes[1] / 2;

    float* base = nullptr;
    cudaGetSymbolAddress((void**)&base, g_buf);
    float* gq   = base + OFF_Q;
    float* gk   = base + OFF_K;
    float* gv   = base + OFF_V;
    float* gp   = base + OFF_P;
    float* gnum = base + OFF_NUM;
    float* gr   = base + OFF_R;
    float* gden = base + OFF_DEN;
    int*   cnt  = (int*)(base + OFF_CNT);
    int*   offs = (int*)(base + OFF_OFFS);
    int*   curs = (int*)(base + OFF_CURS);
    int2*  es   = (int2*)(base + OFF_ES);
    int*   bsum = (int*)(base + OFF_BSUM);
    __nv_bfloat16* xhi = (__nv_bfloat16*)(base + OFF_XHI);
    __nv_bfloat16* xlo = (__nv_bfloat16*)(base + OFF_XLO);
    __nv_bfloat16* wt  = (__nv_bfloat16*)(base + OFF_WT);

    int eb = (E + 255) / 256;
    int nb = (Nn + 1023) / 1024;

    cudaFuncSetAttribute(gemm_mma, cudaFuncAttributeMaxDynamicSharedMemorySize,
                         SMEM_MMA_BYTES);

    // zero only the degree histogram
    cudaMemsetAsync(cnt, 0, (size_t)Nn * sizeof(int), 0);

    // K1-K3: histogram + bf16 prep
    hist_kernel<<<eb, 256>>>(ei, cnt, E);
    split_x<<<(Nn * 32 + 255) / 256, 256>>>(x, xhi, xlo, Nn * 32);
    prep_w<<<dim3(64, 4), 256>>>(Wq, Wk, Wv, Wsk, wt);

    // K4 (ncu capture slot): mma.sync node GEMMs
    gemm_mma<<<dim3((Nn + 127) / 128, 4), 256, SMEM_MMA_BYTES>>>(
        xhi, xlo, wt, bq, bk, bv, bsk, gq, gk, gv, out, Nn);

    // K5-K8: CSR build
    scan_block<<<nb, 1024>>>(cnt, offs, bsum, Nn);
    scan_tops<<<1, 32>>>(bsum, offs, Nn, nb);
    scan_add<<<nb, 1024>>>(offs, curs, bsum, Nn);
    scatter_kernel<<<eb, 256>>>(ei, curs, es, E);

    // K9: p = q contracted with We (per head)
    p_kernel<<<1480, 256>>>(gq, We, gp, Nn);

    // K10: dst-stationary aggregation (no atomics)
    edge_agg<<<(Nn + 7) / 8, 256>>>(offs, es, ea, gq, gk, gv, gp,
                                    gnum, gr, gden, Nn);

    // K11: finalize: rW GEMM + normalize + skip
    finalize_gemm<<<(Nn + 127) / 128, 256>>>(gr, gnum, gden, We, out, Nn);
}